// round 3
// baseline (speedup 1.0000x reference)
#include <cuda_runtime.h>
#include <cuda_bf16.h>
#include <cstdint>

// Shapes (fixed by the problem): B=32, C=256, H=W=64
#define B_DIM 32
#define C_DIM 256
#define HW    4096            // 64*64
#define NTHREADS 256
#define VEC_PER_THREAD 4      // 4 x float4 = 16 floats/thread; 256*16 = 4096

// Decoded style ids (int64-vs-int32 resolved on device). __device__ global:
// allocation-free scratch per harness rules.
__device__ int g_sid[B_DIM];

// style_id may arrive as int64 (reference dtype) or int32 (JAX default x64-off).
// Detection: read the first 32 x 32-bit words (128 bytes — safe for BOTH
// layouts). If the buffer is int64 little-endian with values in [0,16), every
// odd word is 0. If it's int32, odd words are random ids in [0,16); the
// all-zero false positive has probability 16^-16 (~5e-20).
__global__ void decode_sid_kernel(const unsigned int* __restrict__ s) {
    const int t = threadIdx.x;                  // 0..31
    unsigned int oddw = (t < 16) ? s[2 * t + 1] : 0u;
    unsigned int any_nonzero = __ballot_sync(0xFFFFFFFFu, oddw != 0u);
    const bool is_i64 = (any_nonzero == 0u);
    // If int64: value b lives at word 2*b (low half). Max word index 62 < 64 (256B buffer). OK.
    // If int32: value b at word b. OK.
    int v = is_i64 ? (int)s[2 * t] : (int)s[t];
    g_sid[t] = v;
}

__global__ __launch_bounds__(NTHREADS, 1)
void cond_inorm2d_kernel(const float* __restrict__ x,
                         const float* __restrict__ gamma,
                         const float* __restrict__ beta,
                         float* __restrict__ out) {
    const int plane = blockIdx.x;               // b*C + c, 0..8191
    const int b = plane >> 8;                   // C_DIM = 256
    const int c = plane & (C_DIM - 1);

    const float4* __restrict__ xp =
        reinterpret_cast<const float4*>(x) + (size_t)plane * (HW / 4);
    float4* __restrict__ op =
        reinterpret_cast<float4*>(out) + (size_t)plane * (HW / 4);

    const int t = threadIdx.x;

    // ---- Load entire plane slice into registers; accumulate moments ----
    float4 v[VEC_PER_THREAD];
    float s = 0.f, s2 = 0.f;
#pragma unroll
    for (int i = 0; i < VEC_PER_THREAD; i++) {
        v[i] = xp[t + NTHREADS * i];
        s  += v[i].x + v[i].y + v[i].z + v[i].w;
        s2 += v[i].x * v[i].x + v[i].y * v[i].y
            + v[i].z * v[i].z + v[i].w * v[i].w;
    }

    // ---- Warp reduce ----
#pragma unroll
    for (int o = 16; o > 0; o >>= 1) {
        s  += __shfl_xor_sync(0xFFFFFFFFu, s,  o);
        s2 += __shfl_xor_sync(0xFFFFFFFFu, s2, o);
    }

    // ---- Cross-warp reduce (8 warps) ----
    __shared__ float sh_s[8];
    __shared__ float sh_s2[8];
    const int w = t >> 5, l = t & 31;
    if (l == 0) { sh_s[w] = s; sh_s2[w] = s2; }
    __syncthreads();
    if (w == 0) {
        float a  = (l < 8) ? sh_s[l]  : 0.f;
        float a2 = (l < 8) ? sh_s2[l] : 0.f;
#pragma unroll
        for (int o = 4; o > 0; o >>= 1) {
            a  += __shfl_xor_sync(0xFFFFFFFFu, a,  o);
            a2 += __shfl_xor_sync(0xFFFFFFFFu, a2, o);
        }
        if (l == 0) { sh_s[0] = a; sh_s2[0] = a2; }
    }
    __syncthreads();

    const float inv_n = 1.0f / (float)HW;
    const float mean  = sh_s[0] * inv_n;
    const float var   = fmaxf(sh_s2[0] * inv_n - mean * mean, 0.0f);
    const float rstd  = rsqrtf(var + 1e-5f);

    const int sid = g_sid[b];
    const float g  = gamma[sid * C_DIM + c];
    const float be = beta[sid * C_DIM + c];
    const float sc = g * rstd;
    const float sf = be - mean * sc;     // out = x*sc + sf

    // ---- Normalize from registers and store ----
#pragma unroll
    for (int i = 0; i < VEC_PER_THREAD; i++) {
        float4 o4;
        o4.x = v[i].x * sc + sf;
        o4.y = v[i].y * sc + sf;
        o4.z = v[i].z * sc + sf;
        o4.w = v[i].w * sc + sf;
        op[t + NTHREADS * i] = o4;
    }
}

extern "C" void kernel_launch(void* const* d_in, const int* in_sizes, int n_in,
                              void* d_out, int out_size) {
    const float* x           = (const float*)d_in[0];
    const unsigned int* sid  = (const unsigned int*)d_in[1]; // int32 or int64 — decoded on device
    const float* gamma       = (const float*)d_in[2];
    const float* beta        = (const float*)d_in[3];
    float* out               = (float*)d_out;

    decode_sid_kernel<<<1, 32>>>(sid);
    cond_inorm2d_kernel<<<B_DIM * C_DIM, NTHREADS>>>(x, gamma, beta, out);
}

// round 4
// speedup vs baseline: 1.0326x; 1.0326x over previous
#include <cuda_runtime.h>
#include <cuda_bf16.h>
#include <cstdint>

// Shapes (fixed by the problem): B=32, C=256, H=W=64
#define B_DIM 32
#define C_DIM 256
#define HW    4096            // 64*64
#define NTHREADS 256
#define VEC_PER_THREAD 4      // 4 x float4 = 16 floats/thread; 256*16 = 4096

// Single fused kernel. style_id may arrive as int64 (reference dtype) or
// int32 (JAX default with x64 off). Per-CTA detection, thread 0 only:
// read the first 32 x 32-bit words (128 bytes — in-bounds for BOTH layouts).
// int64 little-endian with ids in [0,16) => every odd word is 0.
// int32 => odd words are random ids; all-16-zero probability = 16^-16.
// These 16 scalar loads hit L2/L1 after the first CTA and are issued
// concurrently with the bulk x loads; the result is consumed only after the
// reduction barrier, so they add no critical-path latency.
__global__ __launch_bounds__(NTHREADS, 1)
void cond_inorm2d_kernel(const float* __restrict__ x,
                         const unsigned int* __restrict__ sid_raw,
                         const float* __restrict__ gamma,
                         const float* __restrict__ beta,
                         float* __restrict__ out) {
    const int plane = blockIdx.x;               // b*C + c, 0..8191
    const int b = plane >> 8;                   // C_DIM = 256
    const int c = plane & (C_DIM - 1);

    const float4* __restrict__ xp =
        reinterpret_cast<const float4*>(x) + (size_t)plane * (HW / 4);
    float4* __restrict__ op =
        reinterpret_cast<float4*>(out) + (size_t)plane * (HW / 4);

    const int t = threadIdx.x;

    __shared__ float sh_s[8];
    __shared__ float sh_s2[8];
    __shared__ int   sh_sid;

    // ---- Thread 0: decode style id (dtype-agnostic) ----
    if (t == 0) {
        unsigned int ored = 0u;
#pragma unroll
        for (int i = 1; i < 32; i += 2) ored |= sid_raw[i];
        const bool is_i64 = (ored == 0u);
        sh_sid = is_i64 ? (int)sid_raw[2 * b] : (int)sid_raw[b];
    }

    // ---- Load entire plane slice into registers; accumulate moments ----
    float4 v[VEC_PER_THREAD];
    float s = 0.f, s2 = 0.f;
#pragma unroll
    for (int i = 0; i < VEC_PER_THREAD; i++) {
        v[i] = xp[t + NTHREADS * i];
        s  += v[i].x + v[i].y + v[i].z + v[i].w;
        s2 += v[i].x * v[i].x + v[i].y * v[i].y
            + v[i].z * v[i].z + v[i].w * v[i].w;
    }

    // ---- Warp reduce ----
#pragma unroll
    for (int o = 16; o > 0; o >>= 1) {
        s  += __shfl_xor_sync(0xFFFFFFFFu, s,  o);
        s2 += __shfl_xor_sync(0xFFFFFFFFu, s2, o);
    }

    const int w = t >> 5, l = t & 31;
    if (l == 0) { sh_s[w] = s; sh_s2[w] = s2; }
    __syncthreads();   // single barrier: partials + sh_sid now visible

    // ---- Every warp redundantly reduces the 8 partials (no 2nd barrier) ----
    float a  = (l < 8) ? sh_s[l]  : 0.f;
    float a2 = (l < 8) ? sh_s2[l] : 0.f;
#pragma unroll
    for (int o = 4; o > 0; o >>= 1) {   // xor 4,2,1 stays within 8-lane group
        a  += __shfl_xor_sync(0xFFFFFFFFu, a,  o);
        a2 += __shfl_xor_sync(0xFFFFFFFFu, a2, o);
    }
    const float tot_s  = __shfl_sync(0xFFFFFFFFu, a,  0);
    const float tot_s2 = __shfl_sync(0xFFFFFFFFu, a2, 0);

    const float inv_n = 1.0f / (float)HW;
    const float mean  = tot_s * inv_n;
    const float var   = fmaxf(tot_s2 * inv_n - mean * mean, 0.0f);
    const float rstd  = rsqrtf(var + 1e-5f);

    const int sid = sh_sid;
    const float g  = gamma[sid * C_DIM + c];
    const float be = beta[sid * C_DIM + c];
    const float sc = g * rstd;
    const float sf = be - mean * sc;     // out = x*sc + sf

    // ---- Normalize from registers and store ----
#pragma unroll
    for (int i = 0; i < VEC_PER_THREAD; i++) {
        float4 o4;
        o4.x = v[i].x * sc + sf;
        o4.y = v[i].y * sc + sf;
        o4.z = v[i].z * sc + sf;
        o4.w = v[i].w * sc + sf;
        op[t + NTHREADS * i] = o4;
    }
}

extern "C" void kernel_launch(void* const* d_in, const int* in_sizes, int n_in,
                              void* d_out, int out_size) {
    const float* x          = (const float*)d_in[0];
    const unsigned int* sid = (const unsigned int*)d_in[1]; // int32 or int64
    const float* gamma      = (const float*)d_in[2];
    const float* beta       = (const float*)d_in[3];
    float* out              = (float*)d_out;

    cond_inorm2d_kernel<<<B_DIM * C_DIM, NTHREADS>>>(x, sid, gamma, beta, out);
}